// round 10
// baseline (speedup 1.0000x reference)
#include <cuda_runtime.h>
#include <cuda_bf16.h>
#include <cstdint>

// Problem constants
#define Bn  256
#define Cn  2048
#define HW  196
#define En  16
#define An  3000

// GEMM tiling
#define BT  16      // samples per tile
#define AT  128     // answers per tile
#define KC  32      // K chunk

// Scratch (no cudaMalloc allowed)
__device__ float g_attended[Bn * Cn];      // 2 MB

// ---------------------------------------------------------------------------
// Kernel 1: masked average pooling (unchanged, near BW-bound).
// ---------------------------------------------------------------------------
__global__ __launch_bounds__(256) void pool_kernel(const float* __restrict__ mask,
                                                   const float* __restrict__ feat) {
    int b = blockIdx.x;
    __shared__ float4 s_m4[50];
    __shared__ float  s_inv;
    float* s_m = (float*)s_m4;

    int tid = threadIdx.x;
    if (tid < HW) s_m[tid] = mask[b * HW + tid] + 1e-10f;
    if (tid >= HW && tid < 200) s_m[tid] = 0.0f;
    __syncthreads();

    if (tid < 32) {
        float s = 0.0f;
        for (int i = tid; i < HW; i += 32) s += s_m[i];
        #pragma unroll
        for (int o = 16; o; o >>= 1) s += __shfl_down_sync(0xffffffffu, s, o);
        if (tid == 0) s_inv = 1.0f / s;
    }
    __syncthreads();

    int lane = tid & 31;
    int warp = tid >> 5;
    int c0 = blockIdx.y * 256 + warp * 32;
    float inv = s_inv;

    for (int cc = 0; cc < 32; cc += 4) {
        int c = c0 + cc;
        const float4* r0 = reinterpret_cast<const float4*>(feat + ((size_t)b * Cn + c + 0) * HW);
        const float4* r1 = reinterpret_cast<const float4*>(feat + ((size_t)b * Cn + c + 1) * HW);
        const float4* r2 = reinterpret_cast<const float4*>(feat + ((size_t)b * Cn + c + 2) * HW);
        const float4* r3 = reinterpret_cast<const float4*>(feat + ((size_t)b * Cn + c + 3) * HW);
        float s0 = 0.f, s1 = 0.f, s2 = 0.f, s3 = 0.f;
        #pragma unroll
        for (int i = lane; i < 49; i += 32) {
            float4 m  = s_m4[i];
            float4 v0 = r0[i];
            float4 v1 = r1[i];
            float4 v2 = r2[i];
            float4 v3 = r3[i];
            s0 += v0.x * m.x + v0.y * m.y + v0.z * m.z + v0.w * m.w;
            s1 += v1.x * m.x + v1.y * m.y + v1.z * m.z + v1.w * m.w;
            s2 += v2.x * m.x + v2.y * m.y + v2.z * m.z + v2.w * m.w;
            s3 += v3.x * m.x + v3.y * m.y + v3.z * m.z + v3.w * m.w;
        }
        #pragma unroll
        for (int o = 16; o; o >>= 1) {
            s0 += __shfl_xor_sync(0xffffffffu, s0, o);
            s1 += __shfl_xor_sync(0xffffffffu, s1, o);
            s2 += __shfl_xor_sync(0xffffffffu, s2, o);
            s3 += __shfl_xor_sync(0xffffffffu, s3, o);
        }
        if (lane == 0) {
            *reinterpret_cast<float4*>(&g_attended[(size_t)b * Cn + c]) =
                make_float4(s0 * inv, s1 * inv, s2 * inv, s3 * inv);
        }
    }
}

// ---------------------------------------------------------------------------
// Kernel 2: grouped GEMM, warp = (k-half kh, b-octet o), thread = 4a x 8b.
// grid (24 a-tiles, 16 experts, 2 bt-chunks), block 128 (4 warps).
// W path (LDG -> swizzled transpose STS -> LDS.128) verbatim from R7.
// A duplicated in smem so FFMA2 b-pair operands load directly (no packing).
// k-halves reduced through smem in the epilogue.
// ---------------------------------------------------------------------------
typedef unsigned long long ull;

__device__ __forceinline__ void fma2(ull& d, ull a, ull b) {
    asm("fma.rn.f32x2 %0, %1, %2, %0;" : "+l"(d) : "l"(a), "l"(b));
}

__global__ __launch_bounds__(128) void gemm_kernel(const float* __restrict__ Wmat,
                                                   const float* __restrict__ bias,
                                                   const int* __restrict__ inst_raw,
                                                   float* __restrict__ out) {
    const int e  = blockIdx.y;
    const int a0 = blockIdx.x * AT;
    const int t  = threadIdx.x;
    const int l  = t & 31;
    const int w  = t >> 5;
    const int kh = w >> 1;      // k-half: kk 0-15 / 16-31 of each chunk
    const int o  = w & 1;       // b-octet: b 0-7 / 8-15 of the bt tile

    __shared__ float sW[KC * AT];        // 16 KB swizzled [c][a]; reused as red
    __shared__ float sAd[KC][36];        // [c][2b] duplicated A, padded rows
    __shared__ int   s_list[Bn];
    __shared__ int   s_wcnt[8];

    // ---- fused deterministic grouping (proven R7) ----
    int oddw = inst_raw[2 * t + 1];
    int is64 = __syncthreads_and(oddw == 0);
    int b0i = t, b1i = t + 128;
    int i0 = is64 ? inst_raw[2 * b0i] : inst_raw[b0i];
    int i1 = is64 ? inst_raw[2 * b1i] : inst_raw[b1i];
    unsigned m0 = __ballot_sync(0xffffffffu, i0 == e);
    unsigned m1 = __ballot_sync(0xffffffffu, i1 == e);
    if (l == 0) { s_wcnt[w] = __popc(m0); s_wcnt[4 + w] = __popc(m1); }
    __syncthreads();
    int q0 = s_wcnt[0], q1 = s_wcnt[1], q2 = s_wcnt[2], q3 = s_wcnt[3];
    int q4 = s_wcnt[4], q5 = s_wcnt[5], q6 = s_wcnt[6], q7 = s_wcnt[7];
    int half = q0 + q1 + q2 + q3;
    int n    = half + q4 + q5 + q6 + q7;
    int base0 = (w > 0 ? q0 : 0) + (w > 1 ? q1 : 0) + (w > 2 ? q2 : 0);
    int base1 = half + (w > 0 ? q4 : 0) + (w > 1 ? q5 : 0) + (w > 2 ? q6 : 0);
    unsigned lmask = (1u << l) - 1u;
    if (i0 == e) s_list[base0 + __popc(m0 & lmask)] = b0i;
    if (i1 == e) s_list[base1 + __popc(m1 & lmask)] = b1i;
    __syncthreads();

    // loader lane mappings (verbatim R7)
    const int fr  = t & 7;       // c-granule (16B) within 32-c chunk
    const int rr  = t >> 3;      // a row-in-16
    const int gwu = t >> 5;      // uniform granule part
    const int ca  = t & 7;       // A-loader: c-granule
    const int bq  = t >> 3;      // A-loader: b index (0..15)

    const float* We = Wmat + (size_t)e * An * Cn;

    for (int bt = blockIdx.z * BT; bt < n; bt += 2 * BT) {
        const int active = (bt + 8 * o) < n;   // this warp's octet has work

        ull acc[8][2];
        #pragma unroll
        for (int j = 0; j < 8; j++) { acc[j][0] = 0ull; acc[j][1] = 0ull; }

        float4 wreg[8];
        float4 areg;

        // ---- preload chunk 0 ----
        #pragma unroll
        for (int i = 0; i < 8; i++) {
            int ag = a0 + i * 16 + rr;
            wreg[i] = (ag < An)
                ? *reinterpret_cast<const float4*>(We + (size_t)ag * Cn + fr * 4)
                : make_float4(0.f, 0.f, 0.f, 0.f);
        }
        {
            int idx = bt + bq;
            areg = (idx < n)
                ? *reinterpret_cast<const float4*>(
                      &g_attended[(size_t)s_list[idx] * Cn + ca * 4])
                : make_float4(0.f, 0.f, 0.f, 0.f);
        }

        for (int k0 = 0; k0 < Cn; k0 += KC) {
            __syncthreads();
            // ---- W transpose store (verbatim R7 swizzle) ----
            #pragma unroll
            for (int i = 0; i < 8; i++) {
                int sg = ((i * 4 + gwu) ^ fr);
                int a3 = rr & 3;
                const float* f = (const float*)&wreg[i];
                #pragma unroll
                for (int j = 0; j < 4; j++) {
                    int r = (j << 3) | fr;
                    sW[r * AT + sg * 4 + a3] = f[j];
                }
            }
            // ---- A duplicated store: sAd[c][2b],[2b+1] = v ----
            {
                const float* f = (const float*)&areg;
                #pragma unroll
                for (int j = 0; j < 4; j++) {
                    *reinterpret_cast<float2*>(&sAd[ca * 4 + j][2 * bq]) =
                        make_float2(f[j], f[j]);
                }
            }
            __syncthreads();

            // ---- prefetch next chunk ----
            int kn = k0 + KC;
            if (kn < Cn) {
                #pragma unroll
                for (int i = 0; i < 8; i++) {
                    int ag = a0 + i * 16 + rr;
                    wreg[i] = (ag < An)
                        ? *reinterpret_cast<const float4*>(
                              We + (size_t)ag * Cn + kn + fr * 4)
                        : make_float4(0.f, 0.f, 0.f, 0.f);
                }
                int idx = bt + bq;
                areg = (idx < n)
                    ? *reinterpret_cast<const float4*>(
                          &g_attended[(size_t)s_list[idx] * Cn + kn + ca * 4])
                    : make_float4(0.f, 0.f, 0.f, 0.f);
            }

            // ---- compute: this warp's 16 kk of the chunk ----
            if (active) {
                #pragma unroll
                for (int kk2 = 0; kk2 < 16; kk2++) {
                    int kk = kh * 16 + kk2;
                    int r  = ((kk & 3) << 3) | (kk >> 2); // permuted c-row
                    int xr = kk >> 2;
                    union { float4 f; ull u[2]; } wv;
                    wv.f = *reinterpret_cast<const float4*>(
                        &sW[r * AT + (l ^ xr) * 4]);
                    const float4* ap =
                        reinterpret_cast<const float4*>(&sAd[kk][o * 16]);
                    union { float4 f; ull u[2]; } a01, a23, a45, a67;
                    a01.f = ap[0]; a23.f = ap[1]; a45.f = ap[2]; a67.f = ap[3];
                    fma2(acc[0][0], a01.u[0], wv.u[0]); fma2(acc[0][1], a01.u[0], wv.u[1]);
                    fma2(acc[1][0], a01.u[1], wv.u[0]); fma2(acc[1][1], a01.u[1], wv.u[1]);
                    fma2(acc[2][0], a23.u[0], wv.u[0]); fma2(acc[2][1], a23.u[0], wv.u[1]);
                    fma2(acc[3][0], a23.u[1], wv.u[0]); fma2(acc[3][1], a23.u[1], wv.u[1]);
                    fma2(acc[4][0], a45.u[0], wv.u[0]); fma2(acc[4][1], a45.u[0], wv.u[1]);
                    fma2(acc[5][0], a45.u[1], wv.u[0]); fma2(acc[5][1], a45.u[1], wv.u[1]);
                    fma2(acc[6][0], a67.u[0], wv.u[0]); fma2(acc[6][1], a67.u[0], wv.u[1]);
                    fma2(acc[7][0], a67.u[1], wv.u[0]); fma2(acc[7][1], a67.u[1], wv.u[1]);
                }
            }
        }

        // ---- cross-warp k-half reduction through smem (reuse sW) ----
        __syncthreads();
        float4* red = reinterpret_cast<float4*>(sW);
        if (kh == 1) {
            #pragma unroll
            for (int j = 0; j < 8; j++) {
                union { ull u[2]; float4 f; } v;
                v.u[0] = acc[j][0]; v.u[1] = acc[j][1];
                red[(o * 8 + j) * 32 + l] = v.f;
            }
        }
        __syncthreads();
        if (kh == 0) {
            int abase = a0 + l * 4;
            if (abase < An) {
                float4 b4 = *reinterpret_cast<const float4*>(
                    &bias[(size_t)e * An + abase]);
                #pragma unroll
                for (int j = 0; j < 8; j++) {
                    int idx = bt + 8 * o + j;
                    if (idx < n) {
                        int bg = s_list[idx];
                        float4 r4 = red[(o * 8 + j) * 32 + l];
                        union { ull u[2]; float4 f; } v;
                        v.u[0] = acc[j][0]; v.u[1] = acc[j][1];
                        float4 ov = make_float4(v.f.x + r4.x + b4.x,
                                                v.f.y + r4.y + b4.y,
                                                v.f.z + r4.z + b4.z,
                                                v.f.w + r4.w + b4.w);
                        *reinterpret_cast<float4*>(
                            &out[(size_t)bg * An + abase]) = ov;
                    }
                }
            }
        }
        __syncthreads();   // red reads done before next bt's sW stores
    }
}

// ---------------------------------------------------------------------------
// kernel_launch: identify inputs BY ELEMENT COUNT (immune to metadata order).
//   mask 50176 | features 102760448 | W 98304000 | b 48000 | inst 256
// ---------------------------------------------------------------------------
extern "C" void kernel_launch(void* const* d_in, const int* in_sizes, int n_in,
                              void* d_out, int out_size) {
    const float* mask = nullptr;
    const float* feat = nullptr;
    const float* Wmat = nullptr;
    const float* bias = nullptr;
    const int*   inst = nullptr;

    for (int i = 0; i < n_in; i++) {
        switch (in_sizes[i]) {
            case 50176:     mask = (const float*)d_in[i]; break;
            case 102760448: feat = (const float*)d_in[i]; break;
            case 98304000:  Wmat = (const float*)d_in[i]; break;
            case 48000:     bias = (const float*)d_in[i]; break;
            case 256:       inst = (const int*)  d_in[i]; break;
            default: break;
        }
    }
    float* outp = (float*)d_out;   // [B, A] float32

    pool_kernel<<<dim3(Bn, Cn / 256), 256>>>(mask, feat);
    gemm_kernel<<<dim3((An + AT - 1) / AT, En, 2), 128>>>(Wmat, bias, inst, outp);
}